// round 1
// baseline (speedup 1.0000x reference)
#include <cuda_runtime.h>
#include <math.h>

// ---------------- problem constants ----------------
#define BB 64
#define SS 512
#define HH 768
#define NN 128
#define EE 1024
#define GHD 128
#define FHD 256
#define BNN (BB*NN)          // 8192
#define HCH 192              // H chunk for scatter kernel (4 chunks * 192 = 768)

// ---------------- device scratch (no allocation allowed) ----------------
__device__ float g_gate[BB*SS];          // 32768
__device__ int   g_cnt[BNN];             // 8192
__device__ float g_nf[BNN*HH];           // node features, 25 MB
__device__ float g_A[BB*NN*NN];          // dense normalized adjacency, 4 MB
__device__ float g_H1[BNN*GHD];          // 4 MB
__device__ float g_X1[BNN*GHD];          // 4 MB
__device__ float g_H2[BNN*GHD];          // 4 MB
__device__ float g_pooled[BB*GHD];       // 8192

// ---------------- K0: per-(batch,node) token counts ----------------
__global__ void k_counts(const int* __restrict__ submap) {
    __shared__ int h[NN];
    int b = blockIdx.x, t = threadIdx.x;
    if (t < NN) h[t] = 0;
    __syncthreads();
    for (int s = t; s < SS; s += blockDim.x)
        atomicAdd(&h[submap[b*SS + s]], 1);
    __syncthreads();
    if (t < NN) g_cnt[b*NN + t] = h[t];
}

// ---------------- K1: gate = sigmoid(lh . wr + br), one warp per row ----------------
__global__ void k_gate(const float* __restrict__ lh, const float* __restrict__ wr,
                       const float* __restrict__ brp) {
    int warp = (blockIdx.x * blockDim.x + threadIdx.x) >> 5;
    int lane = threadIdx.x & 31;
    if (warp >= BB*SS) return;
    const float4* row = reinterpret_cast<const float4*>(lh + (size_t)warp * HH);
    const float4* w4  = reinterpret_cast<const float4*>(wr);
    float acc = 0.f;
#pragma unroll
    for (int i = 0; i < 6; i++) {
        float4 v = row[lane + i*32];
        float4 w = w4[lane + i*32];
        acc += v.x*w.x + v.y*w.y + v.z*w.z + v.w*w.w;
    }
#pragma unroll
    for (int o = 16; o; o >>= 1) acc += __shfl_xor_sync(0xffffffffu, acc, o);
    if (lane == 0) g_gate[warp] = 1.f / (1.f + __expf(-(acc + brp[0])));
}

// ---------------- K2: segment-sum of gated rows into node feats (SMEM, no atomics) ----
// grid: (4 chunks, BB batches), block: HCH threads. Thread t owns column c0+t.
__global__ void k_scatter(const float* __restrict__ lh, const int* __restrict__ submap) {
    extern __shared__ float ssum[];        // NN * HCH
    __shared__ int   snode[SS];
    __shared__ float sgate[SS];
    int b  = blockIdx.y;
    int c0 = blockIdx.x * HCH;
    int t  = threadIdx.x;
    for (int i = t; i < NN*HCH; i += HCH) ssum[i] = 0.f;
    for (int s = t; s < SS; s += HCH) {
        snode[s] = submap[b*SS + s];
        sgate[s] = g_gate[b*SS + s];
    }
    __syncthreads();
    const float* base = lh + ((size_t)b * SS) * HH + c0;
    for (int s = 0; s < SS; s += 4) {
        float v0 = base[(size_t)(s+0)*HH + t];
        float v1 = base[(size_t)(s+1)*HH + t];
        float v2 = base[(size_t)(s+2)*HH + t];
        float v3 = base[(size_t)(s+3)*HH + t];
        int n0 = snode[s], n1 = snode[s+1], n2 = snode[s+2], n3 = snode[s+3];
        ssum[n0*HCH + t] += sgate[s]   * v0;
        ssum[n1*HCH + t] += sgate[s+1] * v1;
        ssum[n2*HCH + t] += sgate[s+2] * v2;
        ssum[n3*HCH + t] += sgate[s+3] * v3;
    }
    __syncthreads();
    for (int n = 0; n < NN; n++) {
        int c = g_cnt[b*NN + n];
        float inv = 1.f / (float)(c < 1 ? 1 : c);
        g_nf[((size_t)(b*NN + n)) * HH + c0 + t] = ssum[n*HCH + t] * inv;
    }
}

// ---------------- K3: dense normalized adjacency per batch ----------------
__global__ void k_adj(const int* __restrict__ ei) {
    extern __shared__ float sA[];        // NN*NN
    __shared__ float sdeg[NN];
    __shared__ float sdinv[NN];
    int b = blockIdx.x, t = threadIdx.x;   // 256 threads
    if (t < NN) sdeg[t] = 0.f;
    for (int i = t; i < NN*NN/4; i += 256) {
        float4 z = make_float4(0.f,0.f,0.f,0.f);
        *(float4*)&sA[i*4] = z;
    }
    __syncthreads();
    const int* src = ei + (size_t)b * 2 * EE;
    const int* dst = src + EE;
    for (int e = t; e < EE; e += 256) atomicAdd(&sdeg[dst[e]], 1.f);
    __syncthreads();
    if (t < NN) sdinv[t] = rsqrtf(sdeg[t] + 1.f);   // +1 for self-loop
    __syncthreads();
    for (int e = t; e < EE; e += 256) {
        int s0 = src[e], d0 = dst[e];
        atomicAdd(&sA[d0*NN + s0], sdinv[s0] * sdinv[d0]);
    }
    if (t < NN) atomicAdd(&sA[t*NN + t], sdinv[t] * sdinv[t]);
    __syncthreads();
    float* Ab = g_A + (size_t)b * NN * NN;
    for (int i = t; i < NN*NN/4; i += 256)
        *(float4*)&Ab[i*4] = *(float4*)&sA[i*4];
}

// ---------------- K4/K6: Y[8192,128] = X[8192,KD] @ W[KD,128] (tiled SGEMM) ----------
template<int KD>
__global__ __launch_bounds__(256)
void k_gemm(const float* __restrict__ X, const float* __restrict__ W, float* __restrict__ Y) {
    __shared__ float Ast[16][68];       // transposed A tile, padded
    __shared__ float Bs[16*128];
    int t = threadIdx.x;
    int rowBase = blockIdx.x * 64;
    int trow = t >> 4, tcol = t & 15;
    int aRow = t >> 2, aCol4 = (t & 3) * 4;
    int bRow = t >> 5, bCol = (t & 31) * 4;
    float acc[4][8];
#pragma unroll
    for (int i = 0; i < 4; i++)
#pragma unroll
        for (int j = 0; j < 8; j++) acc[i][j] = 0.f;

    for (int k0 = 0; k0 < KD; k0 += 16) {
        float4 av = *(const float4*)(X + (size_t)(rowBase + aRow)*KD + k0 + aCol4);
        Ast[aCol4+0][aRow] = av.x;
        Ast[aCol4+1][aRow] = av.y;
        Ast[aCol4+2][aRow] = av.z;
        Ast[aCol4+3][aRow] = av.w;
        *(float4*)&Bs[bRow*128 + bCol]     = *(const float4*)(W + (size_t)(k0+bRow)*128 + bCol);
        *(float4*)&Bs[(bRow+8)*128 + bCol] = *(const float4*)(W + (size_t)(k0+bRow+8)*128 + bCol);
        __syncthreads();
#pragma unroll
        for (int kk = 0; kk < 16; kk++) {
            float a[4];
#pragma unroll
            for (int i = 0; i < 4; i++) a[i] = Ast[kk][trow*4 + i];
            float4 b0 = *(float4*)&Bs[kk*128 + tcol*8];
            float4 b1 = *(float4*)&Bs[kk*128 + tcol*8 + 4];
            float bb[8] = {b0.x,b0.y,b0.z,b0.w,b1.x,b1.y,b1.z,b1.w};
#pragma unroll
            for (int i = 0; i < 4; i++)
#pragma unroll
                for (int j = 0; j < 8; j++) acc[i][j] += a[i]*bb[j];
        }
        __syncthreads();
    }
#pragma unroll
    for (int i = 0; i < 4; i++) {
        int r = rowBase + trow*4 + i;
        float4 o0 = make_float4(acc[i][0],acc[i][1],acc[i][2],acc[i][3]);
        float4 o1 = make_float4(acc[i][4],acc[i][5],acc[i][6],acc[i][7]);
        *(float4*)(Y + (size_t)r*128 + tcol*8)     = o0;
        *(float4*)(Y + (size_t)r*128 + tcol*8 + 4) = o1;
    }
}

// ---------------- K5: X1 = relu(A_b @ H1_b + b1), 2 blocks/batch -------------------
__global__ __launch_bounds__(256)
void k_mp1(const float* __restrict__ b1) {
    extern __shared__ float sm[];
    float* As = sm;                 // 64 x 132 (padded)
    float* Hs = sm + 64*132;        // 128 x 128
    int b = blockIdx.x >> 1;
    int rbase = (blockIdx.x & 1) * 64;
    int t = threadIdx.x;
    const float* Ab = g_A  + (size_t)b*NN*NN + (size_t)rbase*NN;
    const float* Hb = g_H1 + (size_t)b*NN*GHD;
    for (int i = t; i < 64*128/4; i += 256) {
        int r = i >> 5, c4 = (i & 31) * 4;
        *(float4*)&As[r*132 + c4] = *(const float4*)(Ab + r*128 + c4);
    }
    for (int i = t; i < 128*128/4; i += 256)
        *(float4*)&Hs[i*4] = *(const float4*)(Hb + i*4);
    __syncthreads();
    int trow = t >> 4, tcol = t & 15;
    float acc[4][8];
#pragma unroll
    for (int i = 0; i < 4; i++)
#pragma unroll
        for (int j = 0; j < 8; j++) acc[i][j] = 0.f;
#pragma unroll 4
    for (int kk = 0; kk < 128; kk++) {
        float a[4];
#pragma unroll
        for (int i = 0; i < 4; i++) a[i] = As[(trow*4 + i)*132 + kk];
        float4 b0 = *(float4*)&Hs[kk*128 + tcol*8];
        float4 b1v = *(float4*)&Hs[kk*128 + tcol*8 + 4];
        float bb[8] = {b0.x,b0.y,b0.z,b0.w,b1v.x,b1v.y,b1v.z,b1v.w};
#pragma unroll
        for (int i = 0; i < 4; i++)
#pragma unroll
            for (int j = 0; j < 8; j++) acc[i][j] += a[i]*bb[j];
    }
    float4 bl0 = *(const float4*)(b1 + tcol*8);
    float4 bl1 = *(const float4*)(b1 + tcol*8 + 4);
    float bias[8] = {bl0.x,bl0.y,bl0.z,bl0.w,bl1.x,bl1.y,bl1.z,bl1.w};
#pragma unroll
    for (int i = 0; i < 4; i++) {
        int r = b*NN + rbase + trow*4 + i;
        float4 o0, o1;
        o0.x = fmaxf(acc[i][0]+bias[0], 0.f); o0.y = fmaxf(acc[i][1]+bias[1], 0.f);
        o0.z = fmaxf(acc[i][2]+bias[2], 0.f); o0.w = fmaxf(acc[i][3]+bias[3], 0.f);
        o1.x = fmaxf(acc[i][4]+bias[4], 0.f); o1.y = fmaxf(acc[i][5]+bias[5], 0.f);
        o1.z = fmaxf(acc[i][6]+bias[6], 0.f); o1.w = fmaxf(acc[i][7]+bias[7], 0.f);
        *(float4*)(g_X1 + (size_t)r*GHD + tcol*8)     = o0;
        *(float4*)(g_X1 + (size_t)r*GHD + tcol*8 + 4) = o1;
    }
}

// ---------------- K7: Z = relu(A_b @ H2_b + b2); pooled[b] = column-mean(Z) --------
__global__ __launch_bounds__(256)
void k_mp2pool(const float* __restrict__ b2) {
    extern __shared__ float sm[];
    float* As = sm;                 // 128 x 132
    float* Hs = sm + 128*132;       // 128 x 128
    int b = blockIdx.x, t = threadIdx.x;
    const float* Ab = g_A  + (size_t)b*NN*NN;
    const float* Hb = g_H2 + (size_t)b*NN*GHD;
    for (int i = t; i < 128*128/4; i += 256) {
        int r = i >> 5, c4 = (i & 31) * 4;
        *(float4*)&As[r*132 + c4] = *(const float4*)(Ab + r*128 + c4);
    }
    for (int i = t; i < 128*128/4; i += 256)
        *(float4*)&Hs[i*4] = *(const float4*)(Hb + i*4);
    __syncthreads();
    int trow = t >> 4, tcol = t & 15;    // 16 row-groups x 16 col-groups
    float acc[8][8];
#pragma unroll
    for (int i = 0; i < 8; i++)
#pragma unroll
        for (int j = 0; j < 8; j++) acc[i][j] = 0.f;
#pragma unroll 2
    for (int kk = 0; kk < 128; kk++) {
        float a[8];
#pragma unroll
        for (int i = 0; i < 8; i++) a[i] = As[(trow*8 + i)*132 + kk];
        float4 b0 = *(float4*)&Hs[kk*128 + tcol*8];
        float4 b1v = *(float4*)&Hs[kk*128 + tcol*8 + 4];
        float bb[8] = {b0.x,b0.y,b0.z,b0.w,b1v.x,b1v.y,b1v.z,b1v.w};
#pragma unroll
        for (int i = 0; i < 8; i++)
#pragma unroll
            for (int j = 0; j < 8; j++) acc[i][j] += a[i]*bb[j];
    }
    float4 bl0 = *(const float4*)(b2 + tcol*8);
    float4 bl1 = *(const float4*)(b2 + tcol*8 + 4);
    float bias[8] = {bl0.x,bl0.y,bl0.z,bl0.w,bl1.x,bl1.y,bl1.z,bl1.w};
    float colp[8];
#pragma unroll
    for (int j = 0; j < 8; j++) colp[j] = 0.f;
#pragma unroll
    for (int i = 0; i < 8; i++)
#pragma unroll
        for (int j = 0; j < 8; j++)
            colp[j] += fmaxf(acc[i][j] + bias[j], 0.f);
    __syncthreads();
    float* red = sm;   // reuse, 16 x 128
#pragma unroll
    for (int j = 0; j < 8; j++) red[trow*128 + tcol*8 + j] = colp[j];
    __syncthreads();
    if (t < 128) {
        float s = 0.f;
#pragma unroll
        for (int r = 0; r < 16; r++) s += red[r*128 + t];
        g_pooled[b*GHD + t] = s * (1.f/128.f);
    }
}

// ---------------- K8: MLP head ----------------
__global__ __launch_bounds__(256)
void k_head(const float* __restrict__ lh, const float* __restrict__ Wf1,
            const float* __restrict__ bf1, const float* __restrict__ Wf2,
            const float* __restrict__ bf2, float* __restrict__ out) {
    __shared__ float xin[HH + GHD];   // 896
    __shared__ float sh[FHD];
    int b = blockIdx.x, t = threadIdx.x;   // 256
    for (int i = t; i < HH; i += 256) xin[i] = lh[((size_t)b*SS)*HH + i];
    if (t < GHD) xin[HH + t] = g_pooled[b*GHD + t];
    __syncthreads();
    float a0 = 0.f, a1 = 0.f, a2 = 0.f, a3 = 0.f;
    for (int k = 0; k < HH + GHD; k += 4) {
        a0 += xin[k+0] * Wf1[(k+0)*FHD + t];
        a1 += xin[k+1] * Wf1[(k+1)*FHD + t];
        a2 += xin[k+2] * Wf1[(k+2)*FHD + t];
        a3 += xin[k+3] * Wf1[(k+3)*FHD + t];
    }
    sh[t] = fmaxf(a0 + a1 + a2 + a3 + bf1[t], 0.f);
    __syncthreads();
    int w = t >> 5, lane = t & 31;
    if (w < 2) {
        float s = 0.f;
        for (int k = lane; k < FHD; k += 32) s += sh[k] * Wf2[k*2 + w];
#pragma unroll
        for (int o = 16; o; o >>= 1) s += __shfl_xor_sync(0xffffffffu, s, o);
        if (lane == 0) out[b*2 + w] = s + bf2[w];
    }
}

// ---------------- launch ----------------
extern "C" void kernel_launch(void* const* d_in, const int* in_sizes, int n_in,
                              void* d_out, int out_size) {
    const float* lh     = (const float*)d_in[0];
    const int*   submap = (const int*)  d_in[1];
    const int*   ei     = (const int*)  d_in[2];
    // d_in[3] = num_nodes (always 128, unused)
    const float* wr  = (const float*)d_in[4];
    const float* br  = (const float*)d_in[5];
    const float* W1  = (const float*)d_in[6];
    const float* b1  = (const float*)d_in[7];
    const float* W2  = (const float*)d_in[8];
    const float* b2  = (const float*)d_in[9];
    const float* Wf1 = (const float*)d_in[10];
    const float* bf1 = (const float*)d_in[11];
    const float* Wf2 = (const float*)d_in[12];
    const float* bf2 = (const float*)d_in[13];
    float* out = (float*)d_out;

    // scratch symbol addresses (host-side API, capture-safe)
    void *p_nf, *p_H1, *p_X1, *p_H2;
    cudaGetSymbolAddress(&p_nf, g_nf);
    cudaGetSymbolAddress(&p_H1, g_H1);
    cudaGetSymbolAddress(&p_X1, g_X1);
    cudaGetSymbolAddress(&p_H2, g_H2);

    const int smem_scatter = NN*HCH*4;                   // 98304
    const int smem_adj     = NN*NN*4;                    // 65536
    const int smem_mp1     = (64*132 + 128*128)*4;       // 99328
    const int smem_mp2     = (128*132 + 128*128)*4;      // 133120
    cudaFuncSetAttribute(k_scatter, cudaFuncAttributeMaxDynamicSharedMemorySize, smem_scatter);
    cudaFuncSetAttribute(k_adj,     cudaFuncAttributeMaxDynamicSharedMemorySize, smem_adj);
    cudaFuncSetAttribute(k_mp1,     cudaFuncAttributeMaxDynamicSharedMemorySize, smem_mp1);
    cudaFuncSetAttribute(k_mp2pool, cudaFuncAttributeMaxDynamicSharedMemorySize, smem_mp2);

    k_counts<<<BB, 128>>>(submap);
    k_gate<<<(BB*SS)/8, 256>>>(lh, wr, br);
    dim3 g2(HH/HCH, BB);
    k_scatter<<<g2, HCH, smem_scatter>>>(lh, submap);
    k_adj<<<BB, 256, smem_adj>>>(ei);
    k_gemm<HH><<<BNN/64, 256>>>((const float*)p_nf, W1, (float*)p_H1);
    k_mp1<<<BB*2, 256, smem_mp1>>>(b1);
    k_gemm<GHD><<<BNN/64, 256>>>((const float*)p_X1, W2, (float*)p_H2);
    k_mp2pool<<<BB, 256, smem_mp2>>>(b2);
    k_head<<<BB, 256>>>(lh, Wf1, bf1, Wf2, bf2, out);
}

// round 2
// speedup vs baseline: 1.2957x; 1.2957x over previous
#include <cuda_runtime.h>
#include <math.h>
#include <stdint.h>

// ---------------- problem constants ----------------
#define BB 64
#define SS 512
#define HH 768
#define NN 128
#define EE 1024
#define GHD 128
#define FHD 256
#define BNN (BB*NN)          // 8192
#define HCH 192              // H chunk for scatter kernel (4 chunks * 192 = 768)

// ---------------- device scratch (no allocation allowed) ----------------
__device__ float g_gate[BB*SS];
__device__ int   g_cnt[BNN];
__device__ float g_nf[BNN*HH];           // node features, 25 MB
__device__ float g_A[BB*NN*NN];          // dense normalized adjacency, 4 MB
__device__ float g_H1[BNN*GHD];
__device__ float g_X1[BNN*GHD];
__device__ float g_H2[BNN*GHD];
__device__ float g_pooled[BB*GHD];

// ---------------- tf32 helpers ----------------
__device__ __forceinline__ float f2tf32(float x) {
    uint32_t u;
    asm("cvt.rna.tf32.f32 %0, %1;" : "=r"(u) : "f"(x));
    return __uint_as_float(u);
}
__device__ __forceinline__ void mma_tf32(float* d, const float* a, const float* b) {
    asm volatile(
        "mma.sync.aligned.m16n8k8.row.col.f32.tf32.tf32.f32 "
        "{%0,%1,%2,%3}, {%4,%5,%6,%7}, {%8,%9}, {%0,%1,%2,%3};"
        : "+f"(d[0]), "+f"(d[1]), "+f"(d[2]), "+f"(d[3])
        : "r"(__float_as_uint(a[0])), "r"(__float_as_uint(a[1])),
          "r"(__float_as_uint(a[2])), "r"(__float_as_uint(a[3])),
          "r"(__float_as_uint(b[0])), "r"(__float_as_uint(b[1])));
}

// ---------------- K0: per-(batch,node) token counts + zero pooled ----------------
__global__ void k_counts(const int* __restrict__ submap) {
    __shared__ int h[NN];
    int b = blockIdx.x, t = threadIdx.x;   // 128 threads
    if (t < NN) h[t] = 0;
    g_pooled[b*GHD + t] = 0.f;             // zero pooled accumulator each replay
    __syncthreads();
    for (int s = t; s < SS; s += blockDim.x)
        atomicAdd(&h[submap[b*SS + s]], 1);
    __syncthreads();
    if (t < NN) g_cnt[b*NN + t] = h[t];
}

// ---------------- K1: gate = sigmoid(lh . wr + br), one warp per row ----------------
__global__ void k_gate(const float* __restrict__ lh, const float* __restrict__ wr,
                       const float* __restrict__ brp) {
    int warp = (blockIdx.x * blockDim.x + threadIdx.x) >> 5;
    int lane = threadIdx.x & 31;
    if (warp >= BB*SS) return;
    const float4* row = reinterpret_cast<const float4*>(lh + (size_t)warp * HH);
    const float4* w4  = reinterpret_cast<const float4*>(wr);
    float acc = 0.f;
#pragma unroll
    for (int i = 0; i < 6; i++) {
        float4 v = row[lane + i*32];
        float4 w = w4[lane + i*32];
        acc += v.x*w.x + v.y*w.y + v.z*w.z + v.w*w.w;
    }
#pragma unroll
    for (int o = 16; o; o >>= 1) acc += __shfl_xor_sync(0xffffffffu, acc, o);
    if (lane == 0) g_gate[warp] = 1.f / (1.f + __expf(-(acc + brp[0])));
}

// ---------------- K2: segment-sum of gated rows into node feats (SMEM, no atomics) ----
__global__ void k_scatter(const float* __restrict__ lh, const int* __restrict__ submap) {
    extern __shared__ float ssum[];        // NN * HCH
    __shared__ int   snode[SS];
    __shared__ float sgate[SS];
    int b  = blockIdx.y;
    int c0 = blockIdx.x * HCH;
    int t  = threadIdx.x;
    for (int i = t; i < NN*HCH; i += HCH) ssum[i] = 0.f;
    for (int s = t; s < SS; s += HCH) {
        snode[s] = submap[b*SS + s];
        sgate[s] = g_gate[b*SS + s];
    }
    __syncthreads();
    const float* base = lh + ((size_t)b * SS) * HH + c0;
    for (int s = 0; s < SS; s += 4) {
        float v0 = base[(size_t)(s+0)*HH + t];
        float v1 = base[(size_t)(s+1)*HH + t];
        float v2 = base[(size_t)(s+2)*HH + t];
        float v3 = base[(size_t)(s+3)*HH + t];
        int n0 = snode[s], n1 = snode[s+1], n2 = snode[s+2], n3 = snode[s+3];
        ssum[n0*HCH + t] += sgate[s]   * v0;
        ssum[n1*HCH + t] += sgate[s+1] * v1;
        ssum[n2*HCH + t] += sgate[s+2] * v2;
        ssum[n3*HCH + t] += sgate[s+3] * v3;
    }
    __syncthreads();
    for (int n = 0; n < NN; n++) {
        int c = g_cnt[b*NN + n];
        float inv = 1.f / (float)(c < 1 ? 1 : c);
        g_nf[((size_t)(b*NN + n)) * HH + c0 + t] = ssum[n*HCH + t] * inv;
    }
}

// ---------------- K3: dense normalized adjacency per batch ----------------
__global__ void k_adj(const int* __restrict__ ei) {
    extern __shared__ float sA[];        // NN*NN
    __shared__ float sdeg[NN];
    __shared__ float sdinv[NN];
    int b = blockIdx.x, t = threadIdx.x;   // 256 threads
    if (t < NN) sdeg[t] = 0.f;
    for (int i = t; i < NN*NN/4; i += 256) {
        float4 z = make_float4(0.f,0.f,0.f,0.f);
        *(float4*)&sA[i*4] = z;
    }
    __syncthreads();
    const int* src = ei + (size_t)b * 2 * EE;
    const int* dst = src + EE;
    for (int e = t; e < EE; e += 256) atomicAdd(&sdeg[dst[e]], 1.f);
    __syncthreads();
    if (t < NN) sdinv[t] = rsqrtf(sdeg[t] + 1.f);   // +1 for self-loop
    __syncthreads();
    for (int e = t; e < EE; e += 256) {
        int s0 = src[e], d0 = dst[e];
        atomicAdd(&sA[d0*NN + s0], sdinv[s0] * sdinv[d0]);
    }
    if (t < NN) atomicAdd(&sA[t*NN + t], sdinv[t] * sdinv[t]);
    __syncthreads();
    float* Ab = g_A + (size_t)b * NN * NN;
    for (int i = t; i < NN*NN/4; i += 256)
        *(float4*)&Ab[i*4] = *(float4*)&sA[i*4];
}

// ---------------- K4/K6: Y[8192,128] = X[8192,KD] @ W[KD,128], tf32 tensor cores ----
// BM=64, BN=128, BK=16. 256 threads = 8 warps (2 m x 4 n), warp tile 32x32.
template<int KD>
__global__ __launch_bounds__(256)
void k_gemm_tc(const float* __restrict__ X, const float* __restrict__ W, float* __restrict__ Y) {
    __shared__ float As[16][72];    // [k][m], pad 72 -> conflict-free frag loads
    __shared__ float Bs[16][136];   // [k][n], pad 136 -> conflict-free frag loads
    int t = threadIdx.x;
    int lane = t & 31, warp = t >> 5;
    int gid = lane >> 2, tig = lane & 3;
    int wm = (warp >> 2) * 32;      // 0 or 32
    int wn = (warp & 3) * 32;       // 0,32,64,96
    int rowBase = blockIdx.x * 64;

    float acc[2][4][4];
#pragma unroll
    for (int i = 0; i < 2; i++)
#pragma unroll
        for (int j = 0; j < 4; j++)
#pragma unroll
            for (int q = 0; q < 4; q++) acc[i][j][q] = 0.f;

    int aM = t & 63;             // 0..63
    int aK = (t >> 6) * 4;       // 0,4,8,12
    int bK = t >> 4;             // 0..15
    int bN = (t & 15) * 8;       // 0..120

    for (int k0 = 0; k0 < KD; k0 += 16) {
        float4 xv = *(const float4*)(X + (size_t)(rowBase + aM)*KD + k0 + aK);
        As[aK+0][aM] = f2tf32(xv.x);
        As[aK+1][aM] = f2tf32(xv.y);
        As[aK+2][aM] = f2tf32(xv.z);
        As[aK+3][aM] = f2tf32(xv.w);
        float4 w0 = *(const float4*)(W + (size_t)(k0+bK)*GHD + bN);
        float4 w1 = *(const float4*)(W + (size_t)(k0+bK)*GHD + bN + 4);
        Bs[bK][bN+0] = f2tf32(w0.x); Bs[bK][bN+1] = f2tf32(w0.y);
        Bs[bK][bN+2] = f2tf32(w0.z); Bs[bK][bN+3] = f2tf32(w0.w);
        Bs[bK][bN+4] = f2tf32(w1.x); Bs[bK][bN+5] = f2tf32(w1.y);
        Bs[bK][bN+6] = f2tf32(w1.z); Bs[bK][bN+7] = f2tf32(w1.w);
        __syncthreads();
#pragma unroll
        for (int ks = 0; ks < 16; ks += 8) {
            float a[2][4], b[4][2];
#pragma unroll
            for (int i = 0; i < 2; i++) {
                a[i][0] = As[ks+tig  ][wm + i*16 + gid];
                a[i][1] = As[ks+tig  ][wm + i*16 + gid + 8];
                a[i][2] = As[ks+tig+4][wm + i*16 + gid];
                a[i][3] = As[ks+tig+4][wm + i*16 + gid + 8];
            }
#pragma unroll
            for (int j = 0; j < 4; j++) {
                b[j][0] = Bs[ks+tig  ][wn + j*8 + gid];
                b[j][1] = Bs[ks+tig+4][wn + j*8 + gid];
            }
#pragma unroll
            for (int i = 0; i < 2; i++)
#pragma unroll
                for (int j = 0; j < 4; j++)
                    mma_tf32(acc[i][j], a[i], b[j]);
        }
        __syncthreads();
    }
#pragma unroll
    for (int i = 0; i < 2; i++)
#pragma unroll
        for (int j = 0; j < 4; j++) {
            int r0 = rowBase + wm + i*16 + gid;
            int c  = wn + j*8 + tig*2;
            *(float2*)(Y + (size_t)r0*GHD + c)     = make_float2(acc[i][j][0], acc[i][j][1]);
            *(float2*)(Y + (size_t)(r0+8)*GHD + c) = make_float2(acc[i][j][2], acc[i][j][3]);
        }
}

// ---------------- K5/K7: batched relu(A_b @ H_b + bias), tf32; optional pooling ----
// grid 2*BB blocks: b = blk>>1, rows rbase=(blk&1)*64. Same tiling as k_gemm_tc.
template<bool POOL>
__global__ __launch_bounds__(256)
void k_gcn_agg(const float* __restrict__ Hin, const float* __restrict__ bias,
               float* __restrict__ Xout) {
    __shared__ float As[16][72];
    __shared__ float Bs[16][136];
    __shared__ float sred[2][GHD];
    extern __shared__ float st[];   // POOL: 64 x 132 output tile
    int t = threadIdx.x;
    int lane = t & 31, warp = t >> 5;
    int gid = lane >> 2, tig = lane & 3;
    int wm = (warp >> 2) * 32;
    int wn = (warp & 3) * 32;
    int b = blockIdx.x >> 1;
    int rbase = (blockIdx.x & 1) * 64;
    const float* A = g_A + (size_t)b*NN*NN;
    const float* H = Hin + (size_t)b*NN*GHD;

    float acc[2][4][4];
#pragma unroll
    for (int i = 0; i < 2; i++)
#pragma unroll
        for (int j = 0; j < 4; j++)
#pragma unroll
            for (int q = 0; q < 4; q++) acc[i][j][q] = 0.f;

    int aM = t & 63;
    int aK = (t >> 6) * 4;
    int bK = t >> 4;
    int bN = (t & 15) * 8;

    for (int k0 = 0; k0 < NN; k0 += 16) {
        float4 xv = *(const float4*)(A + (size_t)(rbase + aM)*NN + k0 + aK);
        As[aK+0][aM] = f2tf32(xv.x);
        As[aK+1][aM] = f2tf32(xv.y);
        As[aK+2][aM] = f2tf32(xv.z);
        As[aK+3][aM] = f2tf32(xv.w);
        float4 w0 = *(const float4*)(H + (size_t)(k0+bK)*GHD + bN);
        float4 w1 = *(const float4*)(H + (size_t)(k0+bK)*GHD + bN + 4);
        Bs[bK][bN+0] = f2tf32(w0.x); Bs[bK][bN+1] = f2tf32(w0.y);
        Bs[bK][bN+2] = f2tf32(w0.z); Bs[bK][bN+3] = f2tf32(w0.w);
        Bs[bK][bN+4] = f2tf32(w1.x); Bs[bK][bN+5] = f2tf32(w1.y);
        Bs[bK][bN+6] = f2tf32(w1.z); Bs[bK][bN+7] = f2tf32(w1.w);
        __syncthreads();
#pragma unroll
        for (int ks = 0; ks < 16; ks += 8) {
            float a[2][4], bf[4][2];
#pragma unroll
            for (int i = 0; i < 2; i++) {
                a[i][0] = As[ks+tig  ][wm + i*16 + gid];
                a[i][1] = As[ks+tig  ][wm + i*16 + gid + 8];
                a[i][2] = As[ks+tig+4][wm + i*16 + gid];
                a[i][3] = As[ks+tig+4][wm + i*16 + gid + 8];
            }
#pragma unroll
            for (int j = 0; j < 4; j++) {
                bf[j][0] = Bs[ks+tig  ][wn + j*8 + gid];
                bf[j][1] = Bs[ks+tig+4][wn + j*8 + gid];
            }
#pragma unroll
            for (int i = 0; i < 2; i++)
#pragma unroll
                for (int j = 0; j < 4; j++)
                    mma_tf32(acc[i][j], a[i], bf[j]);
        }
        __syncthreads();
    }

#pragma unroll
    for (int i = 0; i < 2; i++)
#pragma unroll
        for (int j = 0; j < 4; j++) {
            int rl0 = wm + i*16 + gid;          // local row 0..63
            int c   = wn + j*8 + tig*2;
            float b0 = bias[c], b1 = bias[c+1];
            float v00 = fmaxf(acc[i][j][0] + b0, 0.f);
            float v01 = fmaxf(acc[i][j][1] + b1, 0.f);
            float v10 = fmaxf(acc[i][j][2] + b0, 0.f);
            float v11 = fmaxf(acc[i][j][3] + b1, 0.f);
            if (POOL) {
                st[rl0*132 + c]     = v00;
                st[rl0*132 + c + 1] = v01;
                st[(rl0+8)*132 + c]     = v10;
                st[(rl0+8)*132 + c + 1] = v11;
            } else {
                int r0 = b*NN + rbase + rl0;
                *(float2*)(Xout + (size_t)r0*GHD + c)     = make_float2(v00, v01);
                *(float2*)(Xout + (size_t)(r0+8)*GHD + c) = make_float2(v10, v11);
            }
        }
    if (POOL) {
        __syncthreads();
        int col = t & 127, half = t >> 7;
        float s = 0.f;
#pragma unroll 8
        for (int r = 0; r < 32; r++) s += st[(half*32 + r)*132 + col];
        sred[half][col] = s;
        __syncthreads();
        if (t < GHD)
            atomicAdd(&g_pooled[b*GHD + t], (sred[0][t] + sred[1][t]) * (1.f/128.f));
    }
}

// ---------------- K8: MLP head ----------------
__global__ __launch_bounds__(256)
void k_head(const float* __restrict__ lh, const float* __restrict__ Wf1,
            const float* __restrict__ bf1, const float* __restrict__ Wf2,
            const float* __restrict__ bf2, float* __restrict__ out) {
    __shared__ float xin[HH + GHD];   // 896
    __shared__ float sh[FHD];
    int b = blockIdx.x, t = threadIdx.x;   // 256
    for (int i = t; i < HH; i += 256) xin[i] = lh[((size_t)b*SS)*HH + i];
    if (t < GHD) xin[HH + t] = g_pooled[b*GHD + t];
    __syncthreads();
    float a0 = 0.f, a1 = 0.f, a2 = 0.f, a3 = 0.f;
    for (int k = 0; k < HH + GHD; k += 4) {
        a0 += xin[k+0] * Wf1[(k+0)*FHD + t];
        a1 += xin[k+1] * Wf1[(k+1)*FHD + t];
        a2 += xin[k+2] * Wf1[(k+2)*FHD + t];
        a3 += xin[k+3] * Wf1[(k+3)*FHD + t];
    }
    sh[t] = fmaxf(a0 + a1 + a2 + a3 + bf1[t], 0.f);
    __syncthreads();
    int w = t >> 5, lane = t & 31;
    if (w < 2) {
        float s = 0.f;
        for (int k = lane; k < FHD; k += 32) s += sh[k] * Wf2[k*2 + w];
#pragma unroll
        for (int o = 16; o; o >>= 1) s += __shfl_xor_sync(0xffffffffu, s, o);
        if (lane == 0) out[b*2 + w] = s + bf2[w];
    }
}

// ---------------- launch ----------------
extern "C" void kernel_launch(void* const* d_in, const int* in_sizes, int n_in,
                              void* d_out, int out_size) {
    const float* lh     = (const float*)d_in[0];
    const int*   submap = (const int*)  d_in[1];
    const int*   ei     = (const int*)  d_in[2];
    // d_in[3] = num_nodes (always 128, unused)
    const float* wr  = (const float*)d_in[4];
    const float* br  = (const float*)d_in[5];
    const float* W1  = (const float*)d_in[6];
    const float* b1  = (const float*)d_in[7];
    const float* W2  = (const float*)d_in[8];
    const float* b2  = (const float*)d_in[9];
    const float* Wf1 = (const float*)d_in[10];
    const float* bf1 = (const float*)d_in[11];
    const float* Wf2 = (const float*)d_in[12];
    const float* bf2 = (const float*)d_in[13];
    float* out = (float*)d_out;

    void *p_nf, *p_H1, *p_X1, *p_H2;
    cudaGetSymbolAddress(&p_nf, g_nf);
    cudaGetSymbolAddress(&p_H1, g_H1);
    cudaGetSymbolAddress(&p_X1, g_X1);
    cudaGetSymbolAddress(&p_H2, g_H2);

    const int smem_scatter = NN*HCH*4;                   // 98304
    const int smem_adj     = NN*NN*4;                    // 65536
    const int smem_pool    = 64*132*4;                   // 33792
    cudaFuncSetAttribute(k_scatter, cudaFuncAttributeMaxDynamicSharedMemorySize, smem_scatter);
    cudaFuncSetAttribute(k_adj,     cudaFuncAttributeMaxDynamicSharedMemorySize, smem_adj);

    k_counts<<<BB, 128>>>(submap);
    k_gate<<<(BB*SS)/8, 256>>>(lh, wr, br);
    dim3 g2(HH/HCH, BB);
    k_scatter<<<g2, HCH, smem_scatter>>>(lh, submap);
    k_adj<<<BB, 256, smem_adj>>>(ei);
    k_gemm_tc<HH><<<BNN/64, 256>>>((const float*)p_nf, W1, (float*)p_H1);
    k_gcn_agg<false><<<BB*2, 256, 0>>>((const float*)p_H1, b1, (float*)p_X1);
    k_gemm_tc<GHD><<<BNN/64, 256>>>((const float*)p_X1, W2, (float*)p_H2);
    k_gcn_agg<true><<<BB*2, 256, smem_pool>>>((const float*)p_H2, b2, (float*)p_X1);
    k_head<<<BB, 256>>>(lh, Wf1, bf1, Wf2, bf2, out);
}

// round 4
// speedup vs baseline: 1.3264x; 1.0237x over previous
#include <cuda_runtime.h>
#include <math.h>
#include <stdint.h>

// ---------------- problem constants ----------------
#define BB 64
#define SS 512
#define HH 768
#define NN 128
#define EE 1024
#define GHD 128
#define FHD 256
#define BNN (BB*NN)          // 8192
#define HCH 96               // H chunk for scatter kernel (8 chunks * 96 = 768)

// ---------------- device scratch (no allocation allowed) ----------------
__device__ float g_gate[BB*SS];
__device__ int   g_cnt[BNN];
__device__ float g_nf[BNN*HH];           // node features, 25 MB
__device__ float g_A[BB*NN*NN];          // dense normalized adjacency, 4 MB
__device__ float g_H1[BNN*GHD];
__device__ float g_X1[BNN*GHD];
__device__ float g_H2[BNN*GHD];
__device__ float g_pooled[BB*GHD];

// ---------------- tf32 mma (raw fp32 regs; HW uses top 19 bits) ----------------
__device__ __forceinline__ void mma_tf32(float* d, const float* a, const float* b) {
    asm volatile(
        "mma.sync.aligned.m16n8k8.row.col.f32.tf32.tf32.f32 "
        "{%0,%1,%2,%3}, {%4,%5,%6,%7}, {%8,%9}, {%0,%1,%2,%3};"
        : "+f"(d[0]), "+f"(d[1]), "+f"(d[2]), "+f"(d[3])
        : "r"(__float_as_uint(a[0])), "r"(__float_as_uint(a[1])),
          "r"(__float_as_uint(a[2])), "r"(__float_as_uint(a[3])),
          "r"(__float_as_uint(b[0])), "r"(__float_as_uint(b[1])));
}

// ---------------- K1: dense normalized adjacency, 2 CTAs per batch ----------------
__global__ __launch_bounds__(256)
void k_adj(const int* __restrict__ ei) {
    __shared__ float sA[64*NN];          // 32KB: 64 destination rows x 128 src cols
    __shared__ float sdeg[NN];
    __shared__ float sdinv[NN];
    int b = blockIdx.x >> 1;
    int half = blockIdx.x & 1;
    int lo = half * 64;
    int t = threadIdx.x;                 // 256 threads
    if (t < NN) sdeg[t] = 0.f;
    for (int i = t; i < 64*NN/4; i += 256)
        ((float4*)sA)[i] = make_float4(0.f,0.f,0.f,0.f);
    __syncthreads();
    const int* src = ei + (size_t)b * 2 * EE;
    const int* dst = src + EE;
    for (int e = t; e < EE; e += 256) atomicAdd(&sdeg[dst[e]], 1.f);
    __syncthreads();
    if (t < NN) sdinv[t] = rsqrtf(sdeg[t] + 1.f);   // +1 self-loop
    __syncthreads();
    for (int e = t; e < EE; e += 256) {
        int s0 = src[e], d0 = dst[e];
        if ((d0 >> 6) == half)
            atomicAdd(&sA[(d0 - lo)*NN + s0], sdinv[s0] * sdinv[d0]);
    }
    if (t < 64) {
        int d = lo + t;
        atomicAdd(&sA[t*NN + d], sdinv[d] * sdinv[d]);
    }
    __syncthreads();
    float* Ab = g_A + (size_t)b * NN * NN + (size_t)lo * NN;
    for (int i = t; i < 64*NN/4; i += 256)
        ((float4*)Ab)[i] = ((float4*)sA)[i];
}

// ---------------- K2: token counts + zero pooled ----------------
__global__ void k_counts(const int* __restrict__ submap) {
    __shared__ int h[NN];
    int b = blockIdx.x, t = threadIdx.x;   // 128 threads
    if (t < NN) h[t] = 0;
    g_pooled[b*GHD + t] = 0.f;             // zero pooled accumulator each replay
    __syncthreads();
    for (int s = t; s < SS; s += blockDim.x)
        atomicAdd(&h[submap[b*SS + s]], 1);
    __syncthreads();
    if (t < NN) g_cnt[b*NN + t] = h[t];
}

// ---------------- K3: gate = sigmoid(lh . wr + br) ----------------
__global__ void k_gate(const float* __restrict__ lh, const float* __restrict__ wr,
                       const float* __restrict__ brp) {
    int warp = (blockIdx.x * blockDim.x + threadIdx.x) >> 5;
    int lane = threadIdx.x & 31;
    if (warp >= BB*SS) return;
    const float4* row = reinterpret_cast<const float4*>(lh + (size_t)warp * HH);
    const float4* w4  = reinterpret_cast<const float4*>(wr);
    float acc = 0.f;
#pragma unroll
    for (int i = 0; i < 6; i++) {
        float4 v = row[lane + i*32];
        float4 w = w4[lane + i*32];
        acc += v.x*w.x + v.y*w.y + v.z*w.z + v.w*w.w;
    }
#pragma unroll
    for (int o = 16; o; o >>= 1) acc += __shfl_xor_sync(0xffffffffu, acc, o);
    if (lane == 0) g_gate[warp] = 1.f / (1.f + __expf(-(acc + brp[0])));
}

// ---------------- K4 (PROFILED): segment-sum into node feats ----------------
// grid (8, BB), block 96. Thread t owns column c0+t. ssum = 48KB static exactly.
__global__ __launch_bounds__(96)
void k_scatter(const float* __restrict__ lh, const int* __restrict__ submap) {
    __shared__ float ssum[NN*HCH];       // 49152 bytes (static max)
    int b  = blockIdx.y;
    int c0 = blockIdx.x * HCH;
    int t  = threadIdx.x;
    for (int i = t; i < NN*HCH; i += HCH) ssum[i] = 0.f;
    __syncthreads();
    const float* base = lh + ((size_t)b * SS) * HH + c0;
    const int*   smp  = submap + b*SS;
    const float* gtp  = g_gate + b*SS;
#pragma unroll 1
    for (int s = 0; s < SS; s += 8) {
        float v[8], g[8]; int n[8];
#pragma unroll
        for (int u = 0; u < 8; u++) {
            v[u] = base[(size_t)(s+u)*HH + t];
            n[u] = __ldg(&smp[s+u]);
            g[u] = __ldg(&gtp[s+u]);
        }
#pragma unroll
        for (int u = 0; u < 8; u++)
            ssum[n[u]*HCH + t] += g[u] * v[u];
    }
    // each thread reads only its own column -> no sync needed
    for (int nn = 0; nn < NN; nn++) {
        int c = __ldg(&g_cnt[b*NN + nn]);
        float inv = 1.f / (float)(c < 1 ? 1 : c);
        g_nf[((size_t)(b*NN + nn)) * HH + c0 + t] = ssum[nn*HCH + t] * inv;
    }
}

// ---------------- K5/K7: Y[8192,128] = X[8192,KD] @ W[KD,128], tf32, 2-stage pipe --
// SEL=0: X=g_nf, Y=g_H1. SEL=1: X=g_X1, Y=g_H2.
template<int KD, int SEL>
__global__ __launch_bounds__(256)
void k_gemm_tc(const float* __restrict__ W) {
    const float* __restrict__ X = (SEL == 0) ? g_nf : g_X1;
    float* __restrict__ Y       = (SEL == 0) ? g_H1 : g_H2;
    __shared__ float As[2][16][72];
    __shared__ float Bs[2][16][136];
    int t = threadIdx.x;
    int lane = t & 31, warp = t >> 5;
    int gid = lane >> 2, tig = lane & 3;
    int wm = (warp >> 2) * 32;
    int wn = (warp & 3) * 32;
    int rowBase = blockIdx.x * 64;

    float acc[2][4][4];
#pragma unroll
    for (int i = 0; i < 2; i++)
#pragma unroll
        for (int j = 0; j < 4; j++)
#pragma unroll
            for (int q = 0; q < 4; q++) acc[i][j][q] = 0.f;

    int aM = t & 63;
    int aK = (t >> 6) * 4;
    int bK = t >> 4;
    int bN = (t & 15) * 8;

    float4 xa, wb0, wb1;
    const int NIT = KD / 16;

    xa  = *(const float4*)(X + (size_t)(rowBase + aM)*KD + aK);
    wb0 = *(const float4*)(W + (size_t)bK*GHD + bN);
    wb1 = *(const float4*)(W + (size_t)bK*GHD + bN + 4);
    As[0][aK+0][aM] = xa.x; As[0][aK+1][aM] = xa.y;
    As[0][aK+2][aM] = xa.z; As[0][aK+3][aM] = xa.w;
    *(float4*)&Bs[0][bK][bN]     = wb0;
    *(float4*)&Bs[0][bK][bN + 4] = wb1;

    for (int i = 0; i < NIT; i++) {
        __syncthreads();
        if (i + 1 < NIT) {
            int k0 = (i + 1) * 16;
            xa  = *(const float4*)(X + (size_t)(rowBase + aM)*KD + k0 + aK);
            wb0 = *(const float4*)(W + (size_t)(k0 + bK)*GHD + bN);
            wb1 = *(const float4*)(W + (size_t)(k0 + bK)*GHD + bN + 4);
        }
        const float (*Ac)[72]  = As[i & 1];
        const float (*Bc)[136] = Bs[i & 1];
#pragma unroll
        for (int ks = 0; ks < 16; ks += 8) {
            float a[2][4], bf[4][2];
#pragma unroll
            for (int ii = 0; ii < 2; ii++) {
                a[ii][0] = Ac[ks+tig  ][wm + ii*16 + gid];
                a[ii][1] = Ac[ks+tig  ][wm + ii*16 + gid + 8];
                a[ii][2] = Ac[ks+tig+4][wm + ii*16 + gid];
                a[ii][3] = Ac[ks+tig+4][wm + ii*16 + gid + 8];
            }
#pragma unroll
            for (int j = 0; j < 4; j++) {
                bf[j][0] = Bc[ks+tig  ][wn + j*8 + gid];
                bf[j][1] = Bc[ks+tig+4][wn + j*8 + gid];
            }
#pragma unroll
            for (int ii = 0; ii < 2; ii++)
#pragma unroll
                for (int j = 0; j < 4; j++)
                    mma_tf32(acc[ii][j], a[ii], bf[j]);
        }
        if (i + 1 < NIT) {
            int s = (i + 1) & 1;
            As[s][aK+0][aM] = xa.x; As[s][aK+1][aM] = xa.y;
            As[s][aK+2][aM] = xa.z; As[s][aK+3][aM] = xa.w;
            *(float4*)&Bs[s][bK][bN]     = wb0;
            *(float4*)&Bs[s][bK][bN + 4] = wb1;
        }
    }
#pragma unroll
    for (int i = 0; i < 2; i++)
#pragma unroll
        for (int j = 0; j < 4; j++) {
            int r0 = rowBase + wm + i*16 + gid;
            int c  = wn + j*8 + tig*2;
            *(float2*)(Y + (size_t)r0*GHD + c)     = make_float2(acc[i][j][0], acc[i][j][1]);
            *(float2*)(Y + (size_t)(r0+8)*GHD + c) = make_float2(acc[i][j][2], acc[i][j][3]);
        }
}

// ---------------- K6/K8: batched relu(A_b @ H_b + bias), tf32, 2-stage pipe --------
// POOL=false: Hin=g_H1, out rows -> g_X1. POOL=true: Hin=g_H2, column-mean -> g_pooled.
template<bool POOL>
__global__ __launch_bounds__(256)
void k_gcn_agg(const float* __restrict__ bias) {
    const float* __restrict__ Hin = POOL ? g_H2 : g_H1;
    __shared__ float As[2][16][72];
    __shared__ float Bs[2][16][136];
    __shared__ float sred[GHD];          // 512B pooled partials
    int t = threadIdx.x;
    int lane = t & 31, warp = t >> 5;
    int gid = lane >> 2, tig = lane & 3;
    int wm = (warp >> 2) * 32;
    int wn = (warp & 3) * 32;
    int b = blockIdx.x >> 1;
    int rbase = (blockIdx.x & 1) * 64;
    const float* A = g_A + (size_t)b*NN*NN;
    const float* H = Hin + (size_t)b*NN*GHD;

    if (POOL && t < GHD) sred[t] = 0.f;

    float acc[2][4][4];
#pragma unroll
    for (int i = 0; i < 2; i++)
#pragma unroll
        for (int j = 0; j < 4; j++)
#pragma unroll
            for (int q = 0; q < 4; q++) acc[i][j][q] = 0.f;

    int aM = t & 63;
    int aK = (t >> 6) * 4;
    int bK = t >> 4;
    int bN = (t & 15) * 8;

    float4 xa, wb0, wb1;
    const int NIT = NN / 16;   // 8

    xa  = *(const float4*)(A + (size_t)(rbase + aM)*NN + aK);
    wb0 = *(const float4*)(H + (size_t)bK*GHD + bN);
    wb1 = *(const float4*)(H + (size_t)bK*GHD + bN + 4);
    As[0][aK+0][aM] = xa.x; As[0][aK+1][aM] = xa.y;
    As[0][aK+2][aM] = xa.z; As[0][aK+3][aM] = xa.w;
    *(float4*)&Bs[0][bK][bN]     = wb0;
    *(float4*)&Bs[0][bK][bN + 4] = wb1;

    for (int i = 0; i < NIT; i++) {
        __syncthreads();
        if (i + 1 < NIT) {
            int k0 = (i + 1) * 16;
            xa  = *(const float4*)(A + (size_t)(rbase + aM)*NN + k0 + aK);
            wb0 = *(const float4*)(H + (size_t)(k0 + bK)*GHD + bN);
            wb1 = *(const float4*)(H + (size_t)(k0 + bK)*GHD + bN + 4);
        }
        const float (*Ac)[72]  = As[i & 1];
        const float (*Bc)[136] = Bs[i & 1];
#pragma unroll
        for (int ks = 0; ks < 16; ks += 8) {
            float a[2][4], bf[4][2];
#pragma unroll
            for (int ii = 0; ii < 2; ii++) {
                a[ii][0] = Ac[ks+tig  ][wm + ii*16 + gid];
                a[ii][1] = Ac[ks+tig  ][wm + ii*16 + gid + 8];
                a[ii][2] = Ac[ks+tig+4][wm + ii*16 + gid];
                a[ii][3] = Ac[ks+tig+4][wm + ii*16 + gid + 8];
            }
#pragma unroll
            for (int j = 0; j < 4; j++) {
                bf[j][0] = Bc[ks+tig  ][wn + j*8 + gid];
                bf[j][1] = Bc[ks+tig+4][wn + j*8 + gid];
            }
#pragma unroll
            for (int ii = 0; ii < 2; ii++)
#pragma unroll
                for (int j = 0; j < 4; j++)
                    mma_tf32(acc[ii][j], a[ii], bf[j]);
        }
        if (i + 1 < NIT) {
            int s = (i + 1) & 1;
            As[s][aK+0][aM] = xa.x; As[s][aK+1][aM] = xa.y;
            As[s][aK+2][aM] = xa.z; As[s][aK+3][aM] = xa.w;
            *(float4*)&Bs[s][bK][bN]     = wb0;
            *(float4*)&Bs[s][bK][bN + 4] = wb1;
        }
    }

    if (POOL) {
        float cs[4][2];
#pragma unroll
        for (int j = 0; j < 4; j++) { cs[j][0] = 0.f; cs[j][1] = 0.f; }
#pragma unroll
        for (int i = 0; i < 2; i++)
#pragma unroll
            for (int j = 0; j < 4; j++) {
                int c = wn + j*8 + tig*2;
                float b0 = bias[c], b1 = bias[c+1];
                cs[j][0] += fmaxf(acc[i][j][0] + b0, 0.f) + fmaxf(acc[i][j][2] + b0, 0.f);
                cs[j][1] += fmaxf(acc[i][j][1] + b1, 0.f) + fmaxf(acc[i][j][3] + b1, 0.f);
            }
        // reduce across gid (lane bits 2..4), keep tig lanes distinct
#pragma unroll
        for (int off = 4; off <= 16; off <<= 1)
#pragma unroll
            for (int j = 0; j < 4; j++) {
                cs[j][0] += __shfl_xor_sync(0xffffffffu, cs[j][0], off);
                cs[j][1] += __shfl_xor_sync(0xffffffffu, cs[j][1], off);
            }
        if (gid == 0) {
#pragma unroll
            for (int j = 0; j < 4; j++) {
                atomicAdd(&sred[wn + j*8 + tig*2],     cs[j][0]);
                atomicAdd(&sred[wn + j*8 + tig*2 + 1], cs[j][1]);
            }
        }
        __syncthreads();
        if (t < GHD)
            atomicAdd(&g_pooled[b*GHD + t], sred[t] * (1.f/128.f));
    } else {
#pragma unroll
        for (int i = 0; i < 2; i++)
#pragma unroll
            for (int j = 0; j < 4; j++) {
                int rl0 = wm + i*16 + gid;
                int c   = wn + j*8 + tig*2;
                float b0 = bias[c], b1 = bias[c+1];
                float v00 = fmaxf(acc[i][j][0] + b0, 0.f);
                float v01 = fmaxf(acc[i][j][1] + b1, 0.f);
                float v10 = fmaxf(acc[i][j][2] + b0, 0.f);
                float v11 = fmaxf(acc[i][j][3] + b1, 0.f);
                int r0 = b*NN + rbase + rl0;
                *(float2*)(g_X1 + (size_t)r0*GHD + c)     = make_float2(v00, v01);
                *(float2*)(g_X1 + (size_t)(r0+8)*GHD + c) = make_float2(v10, v11);
            }
    }
}

// ---------------- K9: MLP head ----------------
__global__ __launch_bounds__(256)
void k_head(const float* __restrict__ lh, const float* __restrict__ Wf1,
            const float* __restrict__ bf1, const float* __restrict__ Wf2,
            const float* __restrict__ bf2, float* __restrict__ out) {
    __shared__ float xin[HH + GHD];   // 896
    __shared__ float sh[FHD];
    int b = blockIdx.x, t = threadIdx.x;   // 256
    for (int i = t; i < HH; i += 256) xin[i] = lh[((size_t)b*SS)*HH + i];
    if (t < GHD) xin[HH + t] = g_pooled[b*GHD + t];
    __syncthreads();
    float a0 = 0.f, a1 = 0.f, a2 = 0.f, a3 = 0.f;
    for (int k = 0; k < HH + GHD; k += 4) {
        a0 += xin[k+0] * Wf1[(k+0)*FHD + t];
        a1 += xin[k+1] * Wf1[(k+1)*FHD + t];
        a2 += xin[k+2] * Wf1[(k+2)*FHD + t];
        a3 += xin[k+3] * Wf1[(k+3)*FHD + t];
    }
    sh[t] = fmaxf(a0 + a1 + a2 + a3 + bf1[t], 0.f);
    __syncthreads();
    int w = t >> 5, lane = t & 31;
    if (w < 2) {
        float s = 0.f;
        for (int k = lane; k < FHD; k += 32) s += sh[k] * Wf2[k*2 + w];
#pragma unroll
        for (int o = 16; o; o >>= 1) s += __shfl_xor_sync(0xffffffffu, s, o);
        if (lane == 0) out[b*2 + w] = s + bf2[w];
    }
}

// ---------------- launch: ONLY kernel launches, no other API calls ----------------
extern "C" void kernel_launch(void* const* d_in, const int* in_sizes, int n_in,
                              void* d_out, int out_size) {
    const float* lh     = (const float*)d_in[0];
    const int*   submap = (const int*)  d_in[1];
    const int*   ei     = (const int*)  d_in[2];
    // d_in[3] = num_nodes (always 128, unused)
    const float* wr  = (const float*)d_in[4];
    const float* br  = (const float*)d_in[5];
    const float* W1  = (const float*)d_in[6];
    const float* b1  = (const float*)d_in[7];
    const float* W2  = (const float*)d_in[8];
    const float* b2  = (const float*)d_in[9];
    const float* Wf1 = (const float*)d_in[10];
    const float* bf1 = (const float*)d_in[11];
    const float* Wf2 = (const float*)d_in[12];
    const float* bf2 = (const float*)d_in[13];
    float* out = (float*)d_out;

    k_adj<<<2*BB, 256>>>(ei);                               // 1
    k_counts<<<BB, 128>>>(submap);                          // 2
    k_gate<<<(BB*SS)/8, 256>>>(lh, wr, br);                 // 3
    dim3 g2(HH/HCH, BB);
    k_scatter<<<g2, HCH>>>(lh, submap);                     // 4 <- profiled slot
    k_gemm_tc<HH, 0><<<BNN/64, 256>>>(W1);                  // 5
    k_gcn_agg<false><<<BB*2, 256>>>(b1);                    // 6
    k_gemm_tc<GHD, 1><<<BNN/64, 256>>>(W2);                 // 7
    k_gcn_agg<true><<<BB*2, 256>>>(b2);                     // 8
    k_head<<<BB, 256>>>(lh, Wf1, bf1, Wf2, bf2, out);       // 9
}

// round 5
// speedup vs baseline: 1.3548x; 1.0214x over previous
#include <cuda_runtime.h>
#include <math.h>
#include <stdint.h>

// ---------------- problem constants ----------------
#define BB 64
#define SS 512
#define HH 768
#define NN 128
#define EE 1024
#define GHD 128
#define FHD 256
#define BNN (BB*NN)          // 8192

// ---------------- device scratch (no allocation allowed) ----------------
__device__ float g_gate[BB*SS];
__device__ int   g_cnt[BNN];
__device__ float g_nf[BNN*HH];           // node features, 25 MB
__device__ float g_A[BB*NN*NN];          // dense normalized adjacency, 4 MB
__device__ float g_H1[BNN*GHD];
__device__ float g_X1[BNN*GHD];
__device__ float g_H2[BNN*GHD];
__device__ float g_pooled[BB*GHD];

// ---------------- tf32 mma (raw fp32 regs; HW uses top 19 bits) ----------------
__device__ __forceinline__ void mma_tf32(float* d, const float* a, const float* b) {
    asm volatile(
        "mma.sync.aligned.m16n8k8.row.col.f32.tf32.tf32.f32 "
        "{%0,%1,%2,%3}, {%4,%5,%6,%7}, {%8,%9}, {%0,%1,%2,%3};"
        : "+f"(d[0]), "+f"(d[1]), "+f"(d[2]), "+f"(d[3])
        : "r"(__float_as_uint(a[0])), "r"(__float_as_uint(a[1])),
          "r"(__float_as_uint(a[2])), "r"(__float_as_uint(a[3])),
          "r"(__float_as_uint(b[0])), "r"(__float_as_uint(b[1])));
}

// ---------------- K1: token counts + zero pooled ----------------
__global__ void k_counts(const int* __restrict__ submap) {
    __shared__ int h[NN];
    int b = blockIdx.x, t = threadIdx.x;   // 128 threads
    if (t < NN) h[t] = 0;
    g_pooled[b*GHD + t] = 0.f;             // zero pooled accumulator each replay
    __syncthreads();
    for (int s = t; s < SS; s += blockDim.x)
        atomicAdd(&h[submap[b*SS + s]], 1);
    __syncthreads();
    if (t < NN) g_cnt[b*NN + t] = h[t];
}

// ---------------- K2: gate = sigmoid(lh . wr + br) ----------------
__global__ void k_gate(const float* __restrict__ lh, const float* __restrict__ wr,
                       const float* __restrict__ brp) {
    int warp = (blockIdx.x * blockDim.x + threadIdx.x) >> 5;
    int lane = threadIdx.x & 31;
    if (warp >= BB*SS) return;
    const float4* row = reinterpret_cast<const float4*>(lh + (size_t)warp * HH);
    const float4* w4  = reinterpret_cast<const float4*>(wr);
    float acc = 0.f;
#pragma unroll
    for (int i = 0; i < 6; i++) {
        float4 v = row[lane + i*32];
        float4 w = w4[lane + i*32];
        acc += v.x*w.x + v.y*w.y + v.z*w.z + v.w*w.w;
    }
#pragma unroll
    for (int o = 16; o; o >>= 1) acc += __shfl_xor_sync(0xffffffffu, acc, o);
    if (lane == 0) g_gate[warp] = 1.f / (1.f + __expf(-(acc + brp[0])));
}

// ---------------- K3: segment-mean as tensor-core GEMM ----------------
// node_feats_b = M_b[128,512] @ lh_b[512,768], M built on the fly in smem.
// grid (6 H-tiles, 64 batches), 256 threads = 8 warps (4m x 2n), warp tile 32x64.
__global__ __launch_bounds__(256)
void k_scatter_mm(const float* __restrict__ lh, const int* __restrict__ submap) {
    __shared__ float As[2][16][132];     // M chunk  [k][node], padded
    __shared__ float Bs[2][16][132];     // lh chunk [k][hcol], padded
    __shared__ int   ssub[SS];
    __shared__ float sw[SS];             // gate[s] * inv_cnt[submap[s]]
    __shared__ float sinv[NN];
    int b  = blockIdx.y;
    int c0 = blockIdx.x * 128;
    int t  = threadIdx.x;
    int lane = t & 31, warp = t >> 5;
    int gid = lane >> 2, tig = lane & 3;
    int wm = (warp >> 1) * 32;           // 0,32,64,96
    int wn = (warp & 1) * 64;            // 0,64

    if (t < NN) {
        int c = g_cnt[b*NN + t];
        sinv[t] = 1.f / (float)(c < 1 ? 1 : c);
    }
#pragma unroll
    for (int u = 0; u < 2; u++) ssub[t + u*256] = submap[b*SS + t + u*256];
    __syncthreads();
#pragma unroll
    for (int u = 0; u < 2; u++) {
        int s = t + u*256;
        sw[s] = g_gate[b*SS + s] * sinv[ssub[s]];
    }
    __syncthreads();

    float acc[2][8][4];
#pragma unroll
    for (int i = 0; i < 2; i++)
#pragma unroll
        for (int j = 0; j < 8; j++)
#pragma unroll
            for (int q = 0; q < 4; q++) acc[i][j][q] = 0.f;

    // B tile indexing: thread t loads row bR, cols bC..bC+7 (two float4)
    int bR = t >> 4;             // 0..15
    int bC = (t & 15) * 8;       // 0..120
    const float* Bbase = lh + ((size_t)b * SS) * HH + c0;

    const int NIT = SS / 16;     // 32

    // prologue: build A[0], load B[0]
    {
        // zero A buf 0 (16x128 area)
#pragma unroll
        for (int z = 0; z < 2; z++) {
            int idx = t + z*256;                     // 0..511 float4 slots
            int r = idx >> 5, c4 = (idx & 31) * 4;
            *(float4*)&As[0][r][c4] = make_float4(0.f,0.f,0.f,0.f);
        }
        __syncthreads();
        if (t < 16) As[0][t][ssub[t]] = sw[t];
        float4 v0 = *(const float4*)(Bbase + (size_t)bR*HH + bC);
        float4 v1 = *(const float4*)(Bbase + (size_t)bR*HH + bC + 4);
        *(float4*)&Bs[0][bR][bC]     = v0;
        *(float4*)&Bs[0][bR][bC + 4] = v1;
    }

    for (int i = 0; i < NIT; i++) {
        __syncthreads();
        int cur = i & 1, nxt = cur ^ 1;
        float4 v0, v1;
        if (i + 1 < NIT) {
            int k0 = (i + 1) * 16;
            v0 = *(const float4*)(Bbase + (size_t)(k0 + bR)*HH + bC);
            v1 = *(const float4*)(Bbase + (size_t)(k0 + bR)*HH + bC + 4);
            // zero + scatter next A buffer (not read until after next sync)
#pragma unroll
            for (int z = 0; z < 2; z++) {
                int idx = t + z*256;
                int r = idx >> 5, c4 = (idx & 31) * 4;
                *(float4*)&As[nxt][r][c4] = make_float4(0.f,0.f,0.f,0.f);
            }
        }
#pragma unroll
        for (int ks = 0; ks < 16; ks += 8) {
            float a[2][4], bf[8][2];
#pragma unroll
            for (int ii = 0; ii < 2; ii++) {
                a[ii][0] = As[cur][ks+tig  ][wm + ii*16 + gid];
                a[ii][1] = As[cur][ks+tig  ][wm + ii*16 + gid + 8];
                a[ii][2] = As[cur][ks+tig+4][wm + ii*16 + gid];
                a[ii][3] = As[cur][ks+tig+4][wm + ii*16 + gid + 8];
            }
#pragma unroll
            for (int j = 0; j < 8; j++) {
                bf[j][0] = Bs[cur][ks+tig  ][wn + j*8 + gid];
                bf[j][1] = Bs[cur][ks+tig+4][wn + j*8 + gid];
            }
#pragma unroll
            for (int ii = 0; ii < 2; ii++)
#pragma unroll
                for (int j = 0; j < 8; j++)
                    mma_tf32(acc[ii][j], a[ii], bf[j]);
        }
        if (i + 1 < NIT) {
            int k0 = (i + 1) * 16;
            *(float4*)&Bs[nxt][bR][bC]     = v0;
            *(float4*)&Bs[nxt][bR][bC + 4] = v1;
            __syncthreads();   // A-zero of nxt complete before scatter writes
            if (t < 16) As[nxt][t][ssub[k0 + t]] = sw[k0 + t];
        }
    }

    // epilogue: write node features
#pragma unroll
    for (int ii = 0; ii < 2; ii++)
#pragma unroll
        for (int j = 0; j < 8; j++) {
            int n0 = wm + ii*16 + gid;
            int c  = c0 + wn + j*8 + tig*2;
            *(float2*)(g_nf + ((size_t)(b*NN + n0))*HH + c)     = make_float2(acc[ii][j][0], acc[ii][j][1]);
            *(float2*)(g_nf + ((size_t)(b*NN + n0 + 8))*HH + c) = make_float2(acc[ii][j][2], acc[ii][j][3]);
        }
}

// ---------------- K5: dense normalized adjacency, 2 CTAs per batch ----------------
__global__ __launch_bounds__(256)
void k_adj(const int* __restrict__ ei) {
    __shared__ float sA[64*NN];          // 32KB
    __shared__ float sdeg[NN];
    __shared__ float sdinv[NN];
    int b = blockIdx.x >> 1;
    int half = blockIdx.x & 1;
    int lo = half * 64;
    int t = threadIdx.x;                 // 256 threads
    if (t < NN) sdeg[t] = 0.f;
    for (int i = t; i < 64*NN/4; i += 256)
        ((float4*)sA)[i] = make_float4(0.f,0.f,0.f,0.f);
    __syncthreads();
    const int* src = ei + (size_t)b * 2 * EE;
    const int* dst = src + EE;
    for (int e = t; e < EE; e += 256) atomicAdd(&sdeg[dst[e]], 1.f);
    __syncthreads();
    if (t < NN) sdinv[t] = rsqrtf(sdeg[t] + 1.f);
    __syncthreads();
    for (int e = t; e < EE; e += 256) {
        int s0 = src[e], d0 = dst[e];
        if ((d0 >> 6) == half)
            atomicAdd(&sA[(d0 - lo)*NN + s0], sdinv[s0] * sdinv[d0]);
    }
    if (t < 64) {
        int d = lo + t;
        atomicAdd(&sA[t*NN + d], sdinv[d] * sdinv[d]);
    }
    __syncthreads();
    float* Ab = g_A + (size_t)b * NN * NN + (size_t)lo * NN;
    for (int i = t; i < 64*NN/4; i += 256)
        ((float4*)Ab)[i] = ((float4*)sA)[i];
}

// ---------------- K4/K7 (PROFILED slot 4): Y = X @ W, tf32, 2-stage pipe ----------
template<int KD, int SEL>
__global__ __launch_bounds__(256)
void k_gemm_tc(const float* __restrict__ W) {
    const float* __restrict__ X = (SEL == 0) ? g_nf : g_X1;
    float* __restrict__ Y       = (SEL == 0) ? g_H1 : g_H2;
    __shared__ float As[2][16][72];
    __shared__ float Bs[2][16][136];
    int t = threadIdx.x;
    int lane = t & 31, warp = t >> 5;
    int gid = lane >> 2, tig = lane & 3;
    int wm = (warp >> 2) * 32;
    int wn = (warp & 3) * 32;
    int rowBase = blockIdx.x * 64;

    float acc[2][4][4];
#pragma unroll
    for (int i = 0; i < 2; i++)
#pragma unroll
        for (int j = 0; j < 4; j++)
#pragma unroll
            for (int q = 0; q < 4; q++) acc[i][j][q] = 0.f;

    int aM = t & 63;
    int aK = (t >> 6) * 4;
    int bK = t >> 4;
    int bN = (t & 15) * 8;

    float4 xa, wb0, wb1;
    const int NIT = KD / 16;

    xa  = *(const float4*)(X + (size_t)(rowBase + aM)*KD + aK);
    wb0 = *(const float4*)(W + (size_t)bK*GHD + bN);
    wb1 = *(const float4*)(W + (size_t)bK*GHD + bN + 4);
    As[0][aK+0][aM] = xa.x; As[0][aK+1][aM] = xa.y;
    As[0][aK+2][aM] = xa.z; As[0][aK+3][aM] = xa.w;
    *(float4*)&Bs[0][bK][bN]     = wb0;
    *(float4*)&Bs[0][bK][bN + 4] = wb1;

    for (int i = 0; i < NIT; i++) {
        __syncthreads();
        if (i + 1 < NIT) {
            int k0 = (i + 1) * 16;
            xa  = *(const float4*)(X + (size_t)(rowBase + aM)*KD + k0 + aK);
            wb0 = *(const float4*)(W + (size_t)(k0 + bK)*GHD + bN);
            wb1 = *(const float4*)(W + (size_t)(k0 + bK)*GHD + bN + 4);
        }
        const float (*Ac)[72]  = As[i & 1];
        const float (*Bc)[136] = Bs[i & 1];
#pragma unroll
        for (int ks = 0; ks < 16; ks += 8) {
            float a[2][4], bf[4][2];
#pragma unroll
            for (int ii = 0; ii < 2; ii++) {
                a[ii][0] = Ac[ks+tig  ][wm + ii*16 + gid];
                a[ii][1] = Ac[ks+tig  ][wm + ii*16 + gid + 8];
                a[ii][2] = Ac[ks+tig+4][wm + ii*16 + gid];
                a[ii][3] = Ac[ks+tig+4][wm + ii*16 + gid + 8];
            }
#pragma unroll
            for (int j = 0; j < 4; j++) {
                bf[j][0] = Bc[ks+tig  ][wn + j*8 + gid];
                bf[j][1] = Bc[ks+tig+4][wn + j*8 + gid];
            }
#pragma unroll
            for (int ii = 0; ii < 2; ii++)
#pragma unroll
                for (int j = 0; j < 4; j++)
                    mma_tf32(acc[ii][j], a[ii], bf[j]);
        }
        if (i + 1 < NIT) {
            int s = (i + 1) & 1;
            As[s][aK+0][aM] = xa.x; As[s][aK+1][aM] = xa.y;
            As[s][aK+2][aM] = xa.z; As[s][aK+3][aM] = xa.w;
            *(float4*)&Bs[s][bK][bN]     = wb0;
            *(float4*)&Bs[s][bK][bN + 4] = wb1;
        }
    }
#pragma unroll
    for (int i = 0; i < 2; i++)
#pragma unroll
        for (int j = 0; j < 4; j++) {
            int r0 = rowBase + wm + i*16 + gid;
            int c  = wn + j*8 + tig*2;
            *(float2*)(Y + (size_t)r0*GHD + c)     = make_float2(acc[i][j][0], acc[i][j][1]);
            *(float2*)(Y + (size_t)(r0+8)*GHD + c) = make_float2(acc[i][j][2], acc[i][j][3]);
        }
}

// ---------------- K6/K8: batched relu(A_b @ H_b + bias), tf32, 2-stage pipe --------
template<bool POOL>
__global__ __launch_bounds__(256)
void k_gcn_agg(const float* __restrict__ bias) {
    const float* __restrict__ Hin = POOL ? g_H2 : g_H1;
    __shared__ float As[2][16][72];
    __shared__ float Bs[2][16][136];
    __shared__ float sred[GHD];
    int t = threadIdx.x;
    int lane = t & 31, warp = t >> 5;
    int gid = lane >> 2, tig = lane & 3;
    int wm = (warp >> 2) * 32;
    int wn = (warp & 3) * 32;
    int b = blockIdx.x >> 1;
    int rbase = (blockIdx.x & 1) * 64;
    const float* A = g_A + (size_t)b*NN*NN;
    const float* H = Hin + (size_t)b*NN*GHD;

    if (POOL && t < GHD) sred[t] = 0.f;

    float acc[2][4][4];
#pragma unroll
    for (int i = 0; i < 2; i++)
#pragma unroll
        for (int j = 0; j < 4; j++)
#pragma unroll
            for (int q = 0; q < 4; q++) acc[i][j][q] = 0.f;

    int aM = t & 63;
    int aK = (t >> 6) * 4;
    int bK = t >> 4;
    int bN = (t & 15) * 8;

    float4 xa, wb0, wb1;
    const int NIT = NN / 16;   // 8

    xa  = *(const float4*)(A + (size_t)(rbase + aM)*NN + aK);
    wb0 = *(const float4*)(H + (size_t)bK*GHD + bN);
    wb1 = *(const float4*)(H + (size_t)bK*GHD + bN + 4);
    As[0][aK+0][aM] = xa.x; As[0][aK+1][aM] = xa.y;
    As[0][aK+2][aM] = xa.z; As[0][aK+3][aM] = xa.w;
    *(float4*)&Bs[0][bK][bN]     = wb0;
    *(float4*)&Bs[0][bK][bN + 4] = wb1;

    for (int i = 0; i < NIT; i++) {
        __syncthreads();
        if (i + 1 < NIT) {
            int k0 = (i + 1) * 16;
            xa  = *(const float4*)(A + (size_t)(rbase + aM)*NN + k0 + aK);
            wb0 = *(const float4*)(H + (size_t)(k0 + bK)*GHD + bN);
            wb1 = *(const float4*)(H + (size_t)(k0 + bK)*GHD + bN + 4);
        }
        const float (*Ac)[72]  = As[i & 1];
        const float (*Bc)[136] = Bs[i & 1];
#pragma unroll
        for (int ks = 0; ks < 16; ks += 8) {
            float a[2][4], bf[4][2];
#pragma unroll
            for (int ii = 0; ii < 2; ii++) {
                a[ii][0] = Ac[ks+tig  ][wm + ii*16 + gid];
                a[ii][1] = Ac[ks+tig  ][wm + ii*16 + gid + 8];
                a[ii][2] = Ac[ks+tig+4][wm + ii*16 + gid];
                a[ii][3] = Ac[ks+tig+4][wm + ii*16 + gid + 8];
            }
#pragma unroll
            for (int j = 0; j < 4; j++) {
                bf[j][0] = Bc[ks+tig  ][wn + j*8 + gid];
                bf[j][1] = Bc[ks+tig+4][wn + j*8 + gid];
            }
#pragma unroll
            for (int ii = 0; ii < 2; ii++)
#pragma unroll
                for (int j = 0; j < 4; j++)
                    mma_tf32(acc[ii][j], a[ii], bf[j]);
        }
        if (i + 1 < NIT) {
            int s = (i + 1) & 1;
            As[s][aK+0][aM] = xa.x; As[s][aK+1][aM] = xa.y;
            As[s][aK+2][aM] = xa.z; As[s][aK+3][aM] = xa.w;
            *(float4*)&Bs[s][bK][bN]     = wb0;
            *(float4*)&Bs[s][bK][bN + 4] = wb1;
        }
    }

    if (POOL) {
        float cs[4][2];
#pragma unroll
        for (int j = 0; j < 4; j++) { cs[j][0] = 0.f; cs[j][1] = 0.f; }
#pragma unroll
        for (int i = 0; i < 2; i++)
#pragma unroll
            for (int j = 0; j < 4; j++) {
                int c = wn + j*8 + tig*2;
                float b0 = bias[c], b1 = bias[c+1];
                cs[j][0] += fmaxf(acc[i][j][0] + b0, 0.f) + fmaxf(acc[i][j][2] + b0, 0.f);
                cs[j][1] += fmaxf(acc[i][j][1] + b1, 0.f) + fmaxf(acc[i][j][3] + b1, 0.f);
            }
#pragma unroll
        for (int off = 4; off <= 16; off <<= 1)
#pragma unroll
            for (int j = 0; j < 4; j++) {
                cs[j][0] += __shfl_xor_sync(0xffffffffu, cs[j][0], off);
                cs[j][1] += __shfl_xor_sync(0xffffffffu, cs[j][1], off);
            }
        if (gid == 0) {
#pragma unroll
            for (int j = 0; j < 4; j++) {
                atomicAdd(&sred[wn + j*8 + tig*2],     cs[j][0]);
                atomicAdd(&sred[wn + j*8 + tig*2 + 1], cs[j][1]);
            }
        }
        __syncthreads();
        if (t < GHD)
            atomicAdd(&g_pooled[b*GHD + t], sred[t] * (1.f/128.f));
    } else {
#pragma unroll
        for (int i = 0; i < 2; i++)
#pragma unroll
            for (int j = 0; j < 4; j++) {
                int rl0 = wm + i*16 + gid;
                int c   = wn + j*8 + tig*2;
                float b0 = bias[c], b1 = bias[c+1];
                float v00 = fmaxf(acc[i][j][0] + b0, 0.f);
                float v01 = fmaxf(acc[i][j][1] + b1, 0.f);
                float v10 = fmaxf(acc[i][j][2] + b0, 0.f);
                float v11 = fmaxf(acc[i][j][3] + b1, 0.f);
                int r0 = b*NN + rbase + rl0;
                *(float2*)(g_X1 + (size_t)r0*GHD + c)     = make_float2(v00, v01);
                *(float2*)(g_X1 + (size_t)(r0+8)*GHD + c) = make_float2(v10, v11);
            }
    }
}

// ---------------- K9: MLP head ----------------
__global__ __launch_bounds__(256)
void k_head(const float* __restrict__ lh, const float* __restrict__ Wf1,
            const float* __restrict__ bf1, const float* __restrict__ Wf2,
            const float* __restrict__ bf2, float* __restrict__ out) {
    __shared__ float xin[HH + GHD];
    __shared__ float sh[FHD];
    int b = blockIdx.x, t = threadIdx.x;   // 256
    for (int i = t; i < HH; i += 256) xin[i] = lh[((size_t)b*SS)*HH + i];
    if (t < GHD) xin[HH + t] = g_pooled[b*GHD + t];
    __syncthreads();
    float a0 = 0.f, a1 = 0.f, a2 = 0.f, a3 = 0.f;
    for (int k = 0; k < HH + GHD; k += 4) {
        a0 += xin[k+0] * Wf1[(k+0)*FHD + t];
        a1 += xin[k+1] * Wf1[(k+1)*FHD + t];
        a2 += xin[k+2] * Wf1[(k+2)*FHD + t];
        a3 += xin[k+3] * Wf1[(k+3)*FHD + t];
    }
    sh[t] = fmaxf(a0 + a1 + a2 + a3 + bf1[t], 0.f);
    __syncthreads();
    int w = t >> 5, lane = t & 31;
    if (w < 2) {
        float s = 0.f;
        for (int k = lane; k < FHD; k += 32) s += sh[k] * Wf2[k*2 + w];
#pragma unroll
        for (int o = 16; o; o >>= 1) s += __shfl_xor_sync(0xffffffffu, s, o);
        if (lane == 0) out[b*2 + w] = s + bf2[w];
    }
}

// ---------------- launch: ONLY kernel launches ----------------
extern "C" void kernel_launch(void* const* d_in, const int* in_sizes, int n_in,
                              void* d_out, int out_size) {
    const float* lh     = (const float*)d_in[0];
    const int*   submap = (const int*)  d_in[1];
    const int*   ei     = (const int*)  d_in[2];
    // d_in[3] = num_nodes (always 128, unused)
    const float* wr  = (const float*)d_in[4];
    const float* br  = (const float*)d_in[5];
    const float* W1  = (const float*)d_in[6];
    const float* b1  = (const float*)d_in[7];
    const float* W2  = (const float*)d_in[8];
    const float* b2  = (const float*)d_in[9];
    const float* Wf1 = (const float*)d_in[10];
    const float* bf1 = (const float*)d_in[11];
    const float* Wf2 = (const float*)d_in[12];
    const float* bf2 = (const float*)d_in[13];
    float* out = (float*)d_out;

    k_counts<<<BB, 128>>>(submap);                          // 1
    k_gate<<<(BB*SS)/8, 256>>>(lh, wr, br);                 // 2
    dim3 g3(HH/128, BB);
    k_scatter_mm<<<g3, 256>>>(lh, submap);                  // 3
    k_gemm_tc<HH, 0><<<BNN/64, 256>>>(W1);                  // 4 <- profiled slot
    k_adj<<<2*BB, 256>>>(ei);                               // 5
    k_gcn_agg<false><<<BB*2, 256>>>(b1);                    // 6
    k_gemm_tc<GHD, 1><<<BNN/64, 256>>>(W2);                 // 7
    k_gcn_agg<true><<<BB*2, 256>>>(b2);                     // 8
    k_head<<<BB, 256>>>(lh, Wf1, bf1, Wf2, bf2, out);       // 9
}